// round 16
// baseline (speedup 1.0000x reference)
#include <cuda_runtime.h>
#include <cstdint>

// Problem constants
#define Bsz 32
#define Lsz 4096
#define Isz 128
#define Hsz 256
#define Osz 128
#define NDELAY 5      // delay line length (DELAY+1)

// Scratch (static device globals: allocation-free per harness rules)
__device__ float g_xz[Bsz * Lsz * Hsz];
__device__ float g_xh[Bsz * Lsz * Hsz];
__device__ float g_hs[Bsz * Lsz * Hsz];

// ---------------------------------------------------------------------------
// fp32 tiled GEMM with bias, packed f32x2 accumulation (R10's proven GEMM).
// C[M,N] = A[M,K] @ B[K,N] + bias[N]; 64x64 tile, 256 threads, 4x4 micro.
// ---------------------------------------------------------------------------
__global__ void __launch_bounds__(256) gemm_bias(
    const float* __restrict__ A, const float* __restrict__ Bm,
    const float* __restrict__ bias, float* __restrict__ C,
    int M, int K, int N)
{
    __shared__ float sA[64][68];
    __shared__ float sB[64][68];

    const int m0  = blockIdx.x << 6;
    const int n0  = blockIdx.y << 6;
    const int tid = threadIdx.x;
    const int tx  = tid & 15;
    const int ty  = tid >> 4;

    uint64_t acc01[4], acc23[4];
#pragma unroll
    for (int i = 0; i < 4; i++) { acc01[i] = 0; acc23[i] = 0; }

    for (int kk = 0; kk < K; kk += 64) {
#pragma unroll
        for (int i = 0; i < 4; i++) {
            int lin = tid + (i << 8);
            int r   = lin >> 4;
            int c   = (lin & 15) << 2;
            *(float4*)&sA[r][c] = *(const float4*)&A[(size_t)(m0 + r) * K + kk + c];
            *(float4*)&sB[r][c] = *(const float4*)&Bm[(size_t)(kk + r) * N + n0 + c];
        }
        __syncthreads();

#pragma unroll 16
        for (int k = 0; k < 64; k++) {
            ulonglong2 bb = *(const ulonglong2*)&sB[k][tx << 2];
#pragma unroll
            for (int i = 0; i < 4; i++) {
                float a = sA[(ty << 2) + i][k];
                uint64_t aa;
                asm("mov.b64 %0, {%1, %1};" : "=l"(aa) : "f"(a));
                asm("fma.rn.f32x2 %0, %1, %2, %0;" : "+l"(acc01[i]) : "l"(aa), "l"(bb.x));
                asm("fma.rn.f32x2 %0, %1, %2, %0;" : "+l"(acc23[i]) : "l"(aa), "l"(bb.y));
            }
        }
        __syncthreads();
    }

    float4 bb = *(const float4*)&bias[n0 + (tx << 2)];
#pragma unroll
    for (int i = 0; i < 4; i++) {
        float c0, c1, c2, c3;
        asm("mov.b64 {%0, %1}, %2;" : "=f"(c0), "=f"(c1) : "l"(acc01[i]));
        asm("mov.b64 {%0, %1}, %2;" : "=f"(c2), "=f"(c3) : "l"(acc23[i]));
        float4 o;
        o.x = c0 + bb.x; o.y = c1 + bb.y; o.z = c2 + bb.z; o.w = c3 + bb.w;
        *(float4*)&C[(size_t)(m0 + (ty << 2) + i) * N + n0 + (tx << 2)] = o;
    }
}

// ---------------------------------------------------------------------------
// Fast-math helpers (ex2/rcp approx: rel err ~1e-7)
// ---------------------------------------------------------------------------
__device__ __forceinline__ float ex2_fast(float x) {
    float r; asm("ex2.approx.f32 %0, %1;" : "=f"(r) : "f"(x)); return r;
}
__device__ __forceinline__ float rcp_fast(float x) {
    float r; asm("rcp.approx.f32 %0, %1;" : "=f"(r) : "f"(x)); return r;
}
__device__ __forceinline__ float sigmoid_fast(float x) {
    return rcp_fast(1.f + ex2_fast(-1.4426950408889634f * x));
}
__device__ __forceinline__ float tanh_fast(float x) {
    float e = ex2_fast(2.885390081777927f * x);
    return (e - 1.f) * rcp_fast(e + 1.f);
}

// Packed f32x2 dot over 64 floats; all lanes read the SAME addresses
// (whole-warp broadcast -> conflict-free, 1 wavefront per LDS.128).
__device__ __forceinline__ float dot64_bcast(const float* p, const uint64_t* w) {
    const ulonglong2* v = (const ulonglong2*)p;
    uint64_t a0 = 0, a1 = 0, a2 = 0, a3 = 0;
#pragma unroll
    for (int j = 0; j < 8; j++) {
        ulonglong2 t = v[j];
        asm("fma.rn.f32x2 %0, %1, %2, %0;" : "+l"(a0) : "l"(t.x), "l"(w[2*j]));
        asm("fma.rn.f32x2 %0, %1, %2, %0;" : "+l"(a1) : "l"(t.y), "l"(w[2*j+1]));
    }
#pragma unroll
    for (int j = 8; j < 16; j++) {
        ulonglong2 t = v[j];
        asm("fma.rn.f32x2 %0, %1, %2, %0;" : "+l"(a2) : "l"(t.x), "l"(w[2*j]));
        asm("fma.rn.f32x2 %0, %1, %2, %0;" : "+l"(a3) : "l"(t.y), "l"(w[2*j+1]));
    }
    uint64_t s01, s23, s;
    asm("add.rn.f32x2 %0, %1, %2;" : "=l"(s01) : "l"(a0), "l"(a1));
    asm("add.rn.f32x2 %0, %1, %2;" : "=l"(s23) : "l"(a2), "l"(a3));
    asm("add.rn.f32x2 %0, %1, %2;" : "=l"(s)   : "l"(s01), "l"(s23));
    float lo, hi;
    asm("mov.b64 {%0, %1}, %2;" : "=f"(lo), "=f"(hi) : "l"(s));
    return lo + hi;
}

__device__ __forceinline__ uint64_t pack2(float lo, float hi) {
    uint64_t r; asm("mov.b64 %0, {%1, %2};" : "=l"(r) : "f"(lo), "f"(hi)); return r;
}

__device__ __forceinline__ void mbar_expect_tx(uint32_t mbar, uint32_t bytes) {
    asm volatile("mbarrier.arrive.expect_tx.shared.b64 _, [%0], %1;"
                 :: "r"(mbar), "r"(bytes) : "memory");
}

__device__ __forceinline__ void mbar_wait(uint32_t mbar, uint32_t parity) {
    asm volatile(
        "{\n\t"
        ".reg .pred P;\n\t"
        "WAIT_%=:\n\t"
        "mbarrier.try_wait.parity.acquire.cluster.shared::cta.b64 P, [%0], %1, 10000000;\n\t"
        "@!P bra WAIT_%=;\n\t"
        "}"
        :: "r"(mbar), "r"(parity) : "memory");
}

// DSMEM bulk copy: local smem -> peer smem, complete_tx to peer's mbarrier.
__device__ __forceinline__ void bulk_s2s(uint32_t dst, uint32_t src,
                                         uint32_t bytes, uint32_t mbar) {
    asm volatile(
        "cp.async.bulk.shared::cluster.shared::cta.mbarrier::complete_tx::bytes "
        "[%0], [%1], %2, [%3];"
        :: "r"(dst), "r"(src), "r"(bytes), "r"(mbar) : "memory");
}

__device__ __forceinline__ void fence_async() {
    asm volatile("fence.proxy.async.shared::cta;" ::: "memory");
}

// ---------------------------------------------------------------------------
// Sequential MGRU scan — R10 dataflow with ONE __syncthreads per step.
//
// 32 clusters x 4 CTAs, one cluster per batch row. CTA r owns state indices
// G = [64r, 64r+64) both as hidden columns and as k-rows of Uz/Uh. Thread
// tid (jp = tid) computes BOTH k-partials over G before the push (the
// R11/R13/R15 lesson: nothing may sit between push and wait):
//   pUh(t) = sum_{k in G} a_k(t)   Uh[k,jp],  a(t)=z(t)(.)h(t-1)  LOCAL
//   pUz(t) = sum_{k in G} h_k(t-4) Uz[k,jp]   (feeds z(t+1))
// Warp w (columns 32w..32w+31, destination CTA d=w>>1, half hf=w&1) stages
// its 64 floats [32 pUh | 32 pUz] contiguously and pushes its OWN 256B block
// after __syncwarp — no CTA-wide barrier before the push. Per destination:
// 8 blocks x 256B = 2048 tx-bytes on mb[t&1]. Owners (tid<64) wait, reduce
// 4 (pUh,pUz) pairs, update; ONE __syncthreads ends the step.
//
// Ordering per step (per warp): dots(t) -> stage -> syncwarp -> push(t) ->
// [owners: wait(t) -> update(t)] -> SYNC(t) -> dots(t+1) ...
// Buffer-reuse safety with the single sync:
//   a_loc[t&1]   written at update(t-1) (pre SYNC(t-1)), read at dots(t)
//                (post SYNC(t-1)); next write at update(t+1), which follows
//                wait(t+1) <- all warps' push(t+1) <- SYNC(t) <- dots(t).
//   stage[p]     engine-read at push(t) completes before the tx lands, hence
//                before peer wait(t); rewrite at t+2 follows SYNC(t+1) <-
//                our wait(t+1) <- peer push(t+1) <- peer SYNC(t) <- peer
//                wait(t) <- our tx(t) arrived.
//   inbox[p]     owner-read at update(t) (pre SYNC(t)); peer engine rewrite
//                at t+2 follows peer SYNC(t+1) <- peer wait(t+1) <- our
//                push(t+1) <- our SYNC(t) <- our update(t) reads.
//   hd_ring      update(t) writes slot t%5; dots(t) read slot (t+1)%5 —
//                disjoint; the read slot was written at update(t-4), four
//                syncs earlier.
//   mb[t&1]      phase t+2 traffic follows peers' SYNC(t+1) <- ... <- our
//                wait(t) (phase-t consumption). complete_tx arriving before
//                expect_tx is legal (signed tx count).
// ---------------------------------------------------------------------------
__global__ void __launch_bounds__(256, 1) __cluster_dims__(4, 1, 1)
mgru_scan(const float* __restrict__ xz, const float* __restrict__ xh,
          const float* __restrict__ Uz, const float* __restrict__ Uh,
          float* __restrict__ hs)
{
    __shared__ __align__(16) float a_loc[2][64];        // a(t) local chunk
    __shared__ __align__(16) float hd_ring[NDELAY][64]; // local h history
    __shared__ __align__(16) float stage[2][512];       // [p][warp*64: 32pUh|32pUz]
    __shared__ __align__(16) float inbox[2][512];       // [p][src*128+hf*64: ...]
    __shared__ __align__(8) unsigned long long mb[2];

    const int rank = blockIdx.x & 3;
    const int b    = blockIdx.x >> 2;
    const int tid  = threadIdx.x;
    const int lane = tid & 31;
    const int wid  = tid >> 5;            // warp 0..7
    const int d    = wid >> 1;            // destination CTA of this warp's cols
    const int hf   = wid & 1;             // half within destination slice
    const int jp   = tid;                 // partial column (global, 0..255)

    // Register-resident weight slices: rows k in G, column jp.
    uint64_t wz2[32], wh2[32];
    {
        const float* uz = Uz + (size_t)(rank * 64) * Hsz + jp;
        const float* uh = Uh + (size_t)(rank * 64) * Hsz + jp;
#pragma unroll
        for (int i = 0; i < 32; i++) {
            wz2[i] = pack2(uz[(size_t)(2*i) * Hsz], uz[(size_t)(2*i+1) * Hsz]);
            wh2[i] = pack2(uh[(size_t)(2*i) * Hsz], uh[(size_t)(2*i+1) * Hsz]);
        }
    }

    if (tid == 0) {
        uint32_t m0 = (uint32_t)__cvta_generic_to_shared(&mb[0]);
        asm volatile("mbarrier.init.shared.b64 [%0], 1;" :: "r"(m0) : "memory");
        asm volatile("mbarrier.init.shared.b64 [%0], 1;" :: "r"(m0 + 8) : "memory");
    }
    for (int i = tid; i < 2 * 64;      i += 256) (&a_loc[0][0])[i]   = 0.f;
    for (int i = tid; i < NDELAY * 64; i += 256) (&hd_ring[0][0])[i] = 0.f;
    for (int i = tid; i < 2 * 512;     i += 256) (&stage[0][0])[i]   = 0.f;
    for (int i = tid; i < 2 * 512;     i += 256) (&inbox[0][0])[i]   = 0.f;
    __syncthreads();
    // all CTAs' mbarriers + zeroed buffers visible before any DSMEM traffic
    asm volatile("barrier.cluster.arrive.aligned;" ::: "memory");
    asm volatile("barrier.cluster.wait.aligned;" ::: "memory");

    const uint32_t stage_sa = (uint32_t)__cvta_generic_to_shared(&stage[0][0]);
    const uint32_t inbox_sa = (uint32_t)__cvta_generic_to_shared(&inbox[0][0]);
    const uint32_t mb_sa    = (uint32_t)__cvta_generic_to_shared(&mb[0]);
    uint32_t peer_inbox = 0, peer_mb = 0;   // in CTA `d`'s SMEM (per warp)
    asm("mapa.shared::cluster.u32 %0, %1, %2;" : "=r"(peer_inbox) : "r"(inbox_sa), "r"(d));
    asm("mapa.shared::cluster.u32 %0, %1, %2;" : "=r"(peer_mb)    : "r"(mb_sa),    "r"(d));
    // this warp's 256B stage block and destination block (phase-invariant)
    const uint32_t src_base = stage_sa + (uint32_t)(wid << 8);
    const uint32_t dst_base = peer_inbox + (uint32_t)((rank << 9) + (hf << 8));

    // Column-owner state (threads 0..63): jglob = 64*rank + tid
    const int jglob = rank * 64 + tid;    // valid for tid < 64
    const float* xzp = xz + (size_t)b * Lsz * Hsz + jglob;
    const float* xhp = xh + (size_t)b * Lsz * Hsz + jglob;
    float*       hsp = hs + (size_t)b * Lsz * Hsz + jglob;
    // inbox float index base for this owner's column: tid + (tid & 32)
    const int rb = tid + (tid & 32);

    float h = 0.f, z = 0.f;
    float xh_cur = 0.f, xz_nxt = 0.f, xh_nxt = 0.f;
    if (tid < 64) {
        xh_cur = xhp[0];
        xz_nxt = xzp[Hsz];
        xh_nxt = xhp[Hsz];
        z      = sigmoid_fast(xzp[0]);   // z(0): h(-5) = 0
        // a(0) = z(0)*h(-1) = 0 -> a_loc[0] already zeroed
    }

    int slot_r = 1;  // (t+1)%5 : read h(t-4) feeding z(t+1)
    int slot_w = 0;  // t%5     : write h(t)

    for (int t = 0; t < Lsz; ++t) {
        const int p = t & 1;
        const uint32_t boff = (uint32_t)(p << 3);
        const uint32_t pb   = (uint32_t)(p << 11);   // p*512 floats in bytes

        // ---- both partials from LOCAL chunks (pre-push, critical path)
        float pUh = dot64_bcast(&a_loc[p][0], wh2);
        float pUz = dot64_bcast(&hd_ring[slot_r][0], wz2);
        stage[p][(wid << 6) + lane]      = pUh;
        stage[p][(wid << 6) + 32 + lane] = pUz;

        // ---- warp-autonomous 256B push (no CTA barrier before the push)
        __syncwarp();
        if (lane == 0) {
            fence_async();
            bulk_s2s(dst_base + pb, src_base + pb, 256u, peer_mb + boff);
        }
        if (tid == 0) mbar_expect_tx(mb_sa + boff, 2048u);

        // ---- gmem prefetch (as in R10: only thing between push and wait)
        float xz_p2 = 0.f, xh_p2 = 0.f;
        if (tid < 64 && t + 2 < Lsz) {
            xz_p2 = __ldg(xzp + (size_t)(t + 2) * Hsz);
            xh_p2 = __ldg(xhp + (size_t)(t + 2) * Hsz);
        }

        // ---- owners: acquire-wait, reduce 4 (pUh,pUz) pairs, update state
        if (tid < 64) {
            if (lane == 0) mbar_wait(mb_sa + boff, (uint32_t)((t >> 1) & 1));
            __syncwarp();

            const float* ib = &inbox[p][0];
            float sh = (ib[rb]       + ib[128 + rb])
                     + (ib[256 + rb] + ib[384 + rb]);
            float sz = (ib[32 + rb]       + ib[160 + rb])
                     + (ib[288 + rb] + ib[416 + rb]);
            float ht = tanh_fast(sh + xh_cur);
            h = h + z * (ht - h);                  // h(t)
            float zn = sigmoid_fast(sz + xz_nxt);  // z(t+1)

            a_loc[p ^ 1][tid]    = zn * h;         // a(t+1) local chunk
            hd_ring[slot_w][tid] = h;              // h(t) into ring
            hsp[(size_t)t * Hsz] = h;

            z = zn;
            xh_cur = xh_nxt;
            xz_nxt = xz_p2;
            xh_nxt = xh_p2;
        }
        __syncthreads();   // the ONLY CTA-wide barrier per step

        slot_r = (slot_r == NDELAY - 1) ? 0 : slot_r + 1;
        slot_w = (slot_w == NDELAY - 1) ? 0 : slot_w + 1;
    }

    // no CTA may exit while peer traffic targeting it may be in flight
    asm volatile("barrier.cluster.arrive.aligned;" ::: "memory");
    asm volatile("barrier.cluster.wait.aligned;" ::: "memory");
}

// Dummy so ncu (6th global launch; 2 harness launches precede ours) captures
// the scan: [gemm, gemm, dummy, scan, head].
__global__ void dummy_k() {}

// ---------------------------------------------------------------------------
// Launch: proj GEMMs -> dummy -> scan -> head GEMM
// ---------------------------------------------------------------------------
extern "C" void kernel_launch(void* const* d_in, const int* in_sizes, int n_in,
                              void* d_out, int out_size)
{
    const float* x  = (const float*)d_in[0];
    const float* Wz = (const float*)d_in[1];
    const float* Uz = (const float*)d_in[2];
    const float* bz = (const float*)d_in[3];
    const float* Wh = (const float*)d_in[4];
    const float* Uh = (const float*)d_in[5];
    const float* bh = (const float*)d_in[6];
    const float* Wo = (const float*)d_in[7];
    const float* bo = (const float*)d_in[8];
    float* y = (float*)d_out;

    float *xz_p = nullptr, *xh_p = nullptr, *hs_p = nullptr;
    cudaGetSymbolAddress((void**)&xz_p, g_xz);
    cudaGetSymbolAddress((void**)&xh_p, g_xh);
    cudaGetSymbolAddress((void**)&hs_p, g_hs);

    const int M = Bsz * Lsz;           // 131072
    dim3 blk(256);

    gemm_bias<<<dim3(M / 64, Hsz / 64), blk>>>(x, Wz, bz, xz_p, M, Isz, Hsz);
    gemm_bias<<<dim3(M / 64, Hsz / 64), blk>>>(x, Wh, bh, xh_p, M, Isz, Hsz);

    dummy_k<<<1, 1>>>();

    mgru_scan<<<Bsz * 4, 256>>>(xz_p, xh_p, Uz, Uh, hs_p);

    gemm_bias<<<dim3(M / 64, Osz / 64), blk>>>(hs_p, Wo, bo, y, M, Hsz, Osz);
}

// round 17
// speedup vs baseline: 1.2439x; 1.2439x over previous
#include <cuda_runtime.h>
#include <cstdint>

// Problem constants
#define Bsz 32
#define Lsz 4096
#define Isz 128
#define Hsz 256
#define Osz 128
#define NDELAY 5      // delay line length (DELAY+1)

// Scratch (static device globals: allocation-free per harness rules)
__device__ float g_xz[Bsz * Lsz * Hsz];
__device__ float g_xh[Bsz * Lsz * Hsz];
__device__ float g_hs[Bsz * Lsz * Hsz];

// ---------------------------------------------------------------------------
// fp32 tiled GEMM with bias — k-vectorized A loads + packed f32x2 FMAs.
// C[M,N] = A[M,K] @ B[K,N] + bias[N]; 64x64 tile, 256 threads, 4x4 micro.
// Inner loop processes k in chunks of 4: each A row chunk is ONE LDS.128
// (row stride 68 floats = 272B, k%4==0 -> 16B aligned), each B row is one
// LDS.128. 8 LDS.128 + 32 FMA2 per 4-k chunk per thread (vs 20 LDS before)
// -> halves the L1 wavefront pressure that bound this kernel (L1 was 87%).
// ---------------------------------------------------------------------------
__global__ void __launch_bounds__(256) gemm_bias(
    const float* __restrict__ A, const float* __restrict__ Bm,
    const float* __restrict__ bias, float* __restrict__ C,
    int M, int K, int N)
{
    __shared__ float sA[64][68];
    __shared__ float sB[64][68];

    const int m0  = blockIdx.x << 6;
    const int n0  = blockIdx.y << 6;
    const int tid = threadIdx.x;
    const int tx  = tid & 15;
    const int ty  = tid >> 4;

    uint64_t acc01[4], acc23[4];   // packed (col0,col1)/(col2,col3) per row
#pragma unroll
    for (int i = 0; i < 4; i++) { acc01[i] = 0; acc23[i] = 0; }

    for (int kk = 0; kk < K; kk += 64) {
#pragma unroll
        for (int i = 0; i < 4; i++) {
            int lin = tid + (i << 8);
            int r   = lin >> 4;
            int c   = (lin & 15) << 2;
            *(float4*)&sA[r][c] = *(const float4*)&A[(size_t)(m0 + r) * K + kk + c];
            *(float4*)&sB[r][c] = *(const float4*)&Bm[(size_t)(kk + r) * N + n0 + c];
        }
        __syncthreads();

#pragma unroll
        for (int k = 0; k < 64; k += 4) {
            // A rows: one LDS.128 per row covering k..k+3
            float4 av0 = *(const float4*)&sA[(ty << 2) + 0][k];
            float4 av1 = *(const float4*)&sA[(ty << 2) + 1][k];
            float4 av2 = *(const float4*)&sA[(ty << 2) + 2][k];
            float4 av3 = *(const float4*)&sA[(ty << 2) + 3][k];
#define GEMM_KSTEP(J, COMP)                                                   \
            {                                                                 \
                ulonglong2 bb = *(const ulonglong2*)&sB[k + J][tx << 2];      \
                uint64_t aa;                                                  \
                asm("mov.b64 %0, {%1, %1};" : "=l"(aa) : "f"(av0.COMP));      \
                asm("fma.rn.f32x2 %0, %1, %2, %0;" : "+l"(acc01[0]) : "l"(aa), "l"(bb.x)); \
                asm("fma.rn.f32x2 %0, %1, %2, %0;" : "+l"(acc23[0]) : "l"(aa), "l"(bb.y)); \
                asm("mov.b64 %0, {%1, %1};" : "=l"(aa) : "f"(av1.COMP));      \
                asm("fma.rn.f32x2 %0, %1, %2, %0;" : "+l"(acc01[1]) : "l"(aa), "l"(bb.x)); \
                asm("fma.rn.f32x2 %0, %1, %2, %0;" : "+l"(acc23[1]) : "l"(aa), "l"(bb.y)); \
                asm("mov.b64 %0, {%1, %1};" : "=l"(aa) : "f"(av2.COMP));      \
                asm("fma.rn.f32x2 %0, %1, %2, %0;" : "+l"(acc01[2]) : "l"(aa), "l"(bb.x)); \
                asm("fma.rn.f32x2 %0, %1, %2, %0;" : "+l"(acc23[2]) : "l"(aa), "l"(bb.y)); \
                asm("mov.b64 %0, {%1, %1};" : "=l"(aa) : "f"(av3.COMP));      \
                asm("fma.rn.f32x2 %0, %1, %2, %0;" : "+l"(acc01[3]) : "l"(aa), "l"(bb.x)); \
                asm("fma.rn.f32x2 %0, %1, %2, %0;" : "+l"(acc23[3]) : "l"(aa), "l"(bb.y)); \
            }
            GEMM_KSTEP(0, x)
            GEMM_KSTEP(1, y)
            GEMM_KSTEP(2, z)
            GEMM_KSTEP(3, w)
#undef GEMM_KSTEP
        }
        __syncthreads();
    }

    float4 bb = *(const float4*)&bias[n0 + (tx << 2)];
#pragma unroll
    for (int i = 0; i < 4; i++) {
        float c0, c1, c2, c3;
        asm("mov.b64 {%0, %1}, %2;" : "=f"(c0), "=f"(c1) : "l"(acc01[i]));
        asm("mov.b64 {%0, %1}, %2;" : "=f"(c2), "=f"(c3) : "l"(acc23[i]));
        float4 o;
        o.x = c0 + bb.x; o.y = c1 + bb.y; o.z = c2 + bb.z; o.w = c3 + bb.w;
        *(float4*)&C[(size_t)(m0 + (ty << 2) + i) * N + n0 + (tx << 2)] = o;
    }
}

// ---------------------------------------------------------------------------
// Fast-math helpers (ex2/rcp approx: rel err ~1e-7)
// ---------------------------------------------------------------------------
__device__ __forceinline__ float ex2_fast(float x) {
    float r; asm("ex2.approx.f32 %0, %1;" : "=f"(r) : "f"(x)); return r;
}
__device__ __forceinline__ float rcp_fast(float x) {
    float r; asm("rcp.approx.f32 %0, %1;" : "=f"(r) : "f"(x)); return r;
}
__device__ __forceinline__ float sigmoid_fast(float x) {
    return rcp_fast(1.f + ex2_fast(-1.4426950408889634f * x));
}
__device__ __forceinline__ float tanh_fast(float x) {
    float e = ex2_fast(2.885390081777927f * x);
    return (e - 1.f) * rcp_fast(e + 1.f);
}

// Packed f32x2 dot over 64 floats; all lanes read the SAME addresses
// (whole-warp broadcast -> conflict-free, 1 wavefront per LDS.128).
__device__ __forceinline__ float dot64_bcast(const float* p, const uint64_t* w) {
    const ulonglong2* v = (const ulonglong2*)p;
    uint64_t a0 = 0, a1 = 0, a2 = 0, a3 = 0;
#pragma unroll
    for (int j = 0; j < 8; j++) {
        ulonglong2 t = v[j];
        asm("fma.rn.f32x2 %0, %1, %2, %0;" : "+l"(a0) : "l"(t.x), "l"(w[2*j]));
        asm("fma.rn.f32x2 %0, %1, %2, %0;" : "+l"(a1) : "l"(t.y), "l"(w[2*j+1]));
    }
#pragma unroll
    for (int j = 8; j < 16; j++) {
        ulonglong2 t = v[j];
        asm("fma.rn.f32x2 %0, %1, %2, %0;" : "+l"(a2) : "l"(t.x), "l"(w[2*j]));
        asm("fma.rn.f32x2 %0, %1, %2, %0;" : "+l"(a3) : "l"(t.y), "l"(w[2*j+1]));
    }
    uint64_t s01, s23, s;
    asm("add.rn.f32x2 %0, %1, %2;" : "=l"(s01) : "l"(a0), "l"(a1));
    asm("add.rn.f32x2 %0, %1, %2;" : "=l"(s23) : "l"(a2), "l"(a3));
    asm("add.rn.f32x2 %0, %1, %2;" : "=l"(s)   : "l"(s01), "l"(s23));
    float lo, hi;
    asm("mov.b64 {%0, %1}, %2;" : "=f"(lo), "=f"(hi) : "l"(s));
    return lo + hi;
}

__device__ __forceinline__ uint64_t pack2(float lo, float hi) {
    uint64_t r; asm("mov.b64 %0, {%1, %2};" : "=l"(r) : "f"(lo), "f"(hi)); return r;
}

__device__ __forceinline__ void mbar_expect_tx(uint32_t mbar, uint32_t bytes) {
    asm volatile("mbarrier.arrive.expect_tx.shared.b64 _, [%0], %1;"
                 :: "r"(mbar), "r"(bytes) : "memory");
}

__device__ __forceinline__ void mbar_wait(uint32_t mbar, uint32_t parity) {
    asm volatile(
        "{\n\t"
        ".reg .pred P;\n\t"
        "WAIT_%=:\n\t"
        "mbarrier.try_wait.parity.acquire.cluster.shared::cta.b64 P, [%0], %1, 10000000;\n\t"
        "@!P bra WAIT_%=;\n\t"
        "}"
        :: "r"(mbar), "r"(parity) : "memory");
}

// DSMEM bulk copy: local smem -> peer smem, complete_tx to peer's mbarrier.
__device__ __forceinline__ void bulk_s2s(uint32_t dst, uint32_t src,
                                         uint32_t bytes, uint32_t mbar) {
    asm volatile(
        "cp.async.bulk.shared::cluster.shared::cta.mbarrier::complete_tx::bytes "
        "[%0], [%1], %2, [%3];"
        :: "r"(dst), "r"(src), "r"(bytes), "r"(mbar) : "memory");
}

__device__ __forceinline__ void fence_async() {
    asm volatile("fence.proxy.async.shared::cta;" ::: "memory");
}

// ---------------------------------------------------------------------------
// Sequential MGRU scan — VERBATIM R10 (the empirical optimum across R11-R16;
// every restructure of the exchange lost). FROZEN.
//
// 32 clusters x 4 CTAs, one cluster per batch row. CTA r owns state indices
// G = [64r, 64r+64) both as hidden columns and as k-rows of Uz/Uh. Thread
// tid computes, for global column jp = tid, the k-partial over G:
//     pUh = sum_{k in G} a_k Uh[k, jp],  a = z(t) (.) h(t-1)  (LOCAL chunk)
//     pUz = sum_{k in G} hd_k Uz[k, jp], hd = h(t-4) local    (4-step slack)
// Partial slices (64+64 floats per destination CTA, 512B) are bulk-pushed to
// all 4 CTAs; each CTA's mb[t&1] expects 2048 tx-bytes. After the wait,
// column owners (threads 0..63) sum 4 partials + activations.
//
// Buffer-reuse safety:
//   a_loc[p]    read at step t by all threads before the first __syncthreads;
//               rewritten at step t+2 after the wait chain.
//   out stage[p] bulk-engine source reads for step t complete before peers'
//               wait(t); overwrite at t+2 follows our wait(t+1).
//   inbox[p]    peer rewrite at t+2 follows peer wait(t+1) -> our t+1 push
//               -> our end-sync(t) -> our reads at step t.
//   hd_ring     slot written at end of step t, read at step t+4.
// ---------------------------------------------------------------------------
__global__ void __launch_bounds__(256, 1) __cluster_dims__(4, 1, 1)
mgru_scan(const float* __restrict__ xz, const float* __restrict__ xh,
          const float* __restrict__ Uz, const float* __restrict__ Uh,
          float* __restrict__ hs)
{
    __shared__ __align__(16) float a_loc[2][64];        // a(t) local chunk
    __shared__ __align__(16) float hd_ring[NDELAY][64]; // local h history
    __shared__ __align__(16) float out_stage[2][512];   // [dst4][pUh64|pUz64]
    __shared__ __align__(16) float inbox[2][512];       // [src4][pUh64|pUz64]
    __shared__ __align__(8) unsigned long long mb[2];

    const int rank = blockIdx.x & 3;
    const int b    = blockIdx.x >> 2;
    const int tid  = threadIdx.x;
    const int lane = tid & 31;
    const int jp   = tid;                 // partial column (global, 0..255)
    const int ks   = tid & 3;             // peer index for bulk pushes (tid<4)

    // Register-resident weight slices: rows k in G, column jp.
    uint64_t wz2[32], wh2[32];
    {
        const float* uz = Uz + (size_t)(rank * 64) * Hsz + jp;
        const float* uh = Uh + (size_t)(rank * 64) * Hsz + jp;
#pragma unroll
        for (int i = 0; i < 32; i++) {
            wz2[i] = pack2(uz[(size_t)(2*i) * Hsz], uz[(size_t)(2*i+1) * Hsz]);
            wh2[i] = pack2(uh[(size_t)(2*i) * Hsz], uh[(size_t)(2*i+1) * Hsz]);
        }
    }

    if (tid == 0) {
        uint32_t m0 = (uint32_t)__cvta_generic_to_shared(&mb[0]);
        asm volatile("mbarrier.init.shared.b64 [%0], 1;" :: "r"(m0) : "memory");
        asm volatile("mbarrier.init.shared.b64 [%0], 1;" :: "r"(m0 + 8) : "memory");
    }
    for (int i = tid; i < 2 * 64;      i += 256) (&a_loc[0][0])[i]     = 0.f;
    for (int i = tid; i < NDELAY * 64; i += 256) (&hd_ring[0][0])[i]   = 0.f;
    for (int i = tid; i < 2 * 512;     i += 256) (&out_stage[0][0])[i] = 0.f;
    for (int i = tid; i < 2 * 512;     i += 256) (&inbox[0][0])[i]     = 0.f;
    __syncthreads();
    // all CTAs' mbarriers + zeroed buffers visible before any async traffic
    asm volatile("barrier.cluster.arrive.aligned;" ::: "memory");
    asm volatile("barrier.cluster.wait.aligned;" ::: "memory");

    const uint32_t stage_sa = (uint32_t)__cvta_generic_to_shared(&out_stage[0][0]);
    const uint32_t inbox_sa = (uint32_t)__cvta_generic_to_shared(&inbox[0][0]);
    const uint32_t mb_sa    = (uint32_t)__cvta_generic_to_shared(&mb[0]);
    uint32_t peer_inbox = 0, peer_mb = 0;   // in rank ks's SMEM (tid 0..3)
    asm("mapa.shared::cluster.u32 %0, %1, %2;" : "=r"(peer_inbox) : "r"(inbox_sa), "r"(ks));
    asm("mapa.shared::cluster.u32 %0, %1, %2;" : "=r"(peer_mb)    : "r"(mb_sa),    "r"(ks));

    // Column-owner state (threads 0..63): jglob = 64*rank + tid
    const int jglob = rank * 64 + tid;    // valid for tid < 64
    const float* xzp = xz + (size_t)b * Lsz * Hsz + jglob;
    const float* xhp = xh + (size_t)b * Lsz * Hsz + jglob;
    float*       hsp = hs + (size_t)b * Lsz * Hsz + jglob;

    float h = 0.f, z = 0.f;
    float xh_cur = 0.f, xz_nxt = 0.f, xh_nxt = 0.f;
    if (tid < 64) {
        xh_cur = xhp[0];
        xz_nxt = xzp[Hsz];
        xh_nxt = xhp[Hsz];
        z      = sigmoid_fast(xzp[0]);   // z(0): h(-5) = 0
        // a(0) = z(0)*h(-1) = 0 -> a_loc[0] already zeroed
    }

    int slot_r = 1;  // (t+1)%5 : read h(t-4)
    int slot_w = 0;  // t%5     : write h(t)

    for (int t = 0; t < Lsz; ++t) {
        const int p = t & 1;
        const uint32_t boff = (uint32_t)(p << 3);
        const uint32_t pb   = (uint32_t)(p << 11);   // p*512 floats in bytes

        // ---- partial dots from LOCAL chunks (all 256 threads)
        float pUh = dot64_bcast(&a_loc[p][0], wh2);            // for h(t)
        float pUz = dot64_bcast(&hd_ring[slot_r][0], wz2);     // for z(t+1)
        {
            const int dst = jp >> 6, idx = jp & 63;
            out_stage[p][dst * 128 + idx]      = pUh;
            out_stage[p][dst * 128 + 64 + idx] = pUz;
        }
        __syncthreads();

        // ---- push partial slices to all 4 CTAs (512B each)
        if (tid < 4) {
            fence_async();
            bulk_s2s(peer_inbox + pb + (uint32_t)(rank << 9),
                     stage_sa + pb + (uint32_t)(ks << 9),
                     512u, peer_mb + boff);
        }

        // ---- prefetch (shadow)
        float xz_p2 = 0.f, xh_p2 = 0.f;
        if (tid < 64 && t + 2 < Lsz) {
            xz_p2 = __ldg(xzp + (size_t)(t + 2) * Hsz);
            xh_p2 = __ldg(xhp + (size_t)(t + 2) * Hsz);
        }

        if (tid == 0) mbar_expect_tx(mb_sa + boff, 2048u);

        // ---- only column-owner warps need the wait; others run to the sync
        if (tid < 64) {
            if (lane == 0) mbar_wait(mb_sa + boff, (uint32_t)((t >> 1) & 1));
            __syncwarp();

            // sum 4 partials + activations + state update
            const float* ib = &inbox[p][0];
            float sh = (ib[tid]       + ib[128 + tid])
                     + (ib[256 + tid] + ib[384 + tid]);
            float sz = (ib[64 + tid]       + ib[192 + tid])
                     + (ib[320 + tid] + ib[448 + tid]);
            float ht = tanh_fast(sh + xh_cur);
            h = h + z * (ht - h);                  // h(t)
            float zn = sigmoid_fast(sz + xz_nxt);  // z(t+1)

            a_loc[p ^ 1][tid]   = zn * h;          // a(t+1) local chunk
            hd_ring[slot_w][tid] = h;              // h(t) into ring
            hsp[(size_t)t * Hsz] = h;

            z = zn;
            xh_cur = xh_nxt;
            xz_nxt = xz_p2;
            xh_nxt = xh_p2;
        }
        __syncthreads();

        slot_r = (slot_r == NDELAY - 1) ? 0 : slot_r + 1;
        slot_w = (slot_w == NDELAY - 1) ? 0 : slot_w + 1;
    }

    // no CTA may exit while peer traffic targeting it may be in flight
    asm volatile("barrier.cluster.arrive.aligned;" ::: "memory");
    asm volatile("barrier.cluster.wait.aligned;" ::: "memory");
}

// Dummy so ncu (6th global launch; 2 harness launches precede ours) lands on
// the FIRST proj gemm this time: [gemm, gemm, dummy, scan, head] -> #4 is our
// 2nd launch... keep layout identical to R10 so the scan stays comparable.
__global__ void dummy_k() {}

// ---------------------------------------------------------------------------
// Launch: proj GEMMs -> dummy -> scan -> head GEMM
// ---------------------------------------------------------------------------
extern "C" void kernel_launch(void* const* d_in, const int* in_sizes, int n_in,
                              void* d_out, int out_size)
{
    const float* x  = (const float*)d_in[0];
    const float* Wz = (const float*)d_in[1];
    const float* Uz = (const float*)d_in[2];
    const float* bz = (const float*)d_in[3];
    const float* Wh = (const float*)d_in[4];
    const float* Uh = (const float*)d_in[5];
    const float* bh = (const float*)d_in[6];
    const float* Wo = (const float*)d_in[7];
    const float* bo = (const float*)d_in[8];
    float* y = (float*)d_out;

    float *xz_p = nullptr, *xh_p = nullptr, *hs_p = nullptr;
    cudaGetSymbolAddress((void**)&xz_p, g_xz);
    cudaGetSymbolAddress((void**)&xh_p, g_xh);
    cudaGetSymbolAddress((void**)&hs_p, g_hs);

    const int M = Bsz * Lsz;           // 131072
    dim3 blk(256);

    gemm_bias<<<dim3(M / 64, Hsz / 64), blk>>>(x, Wz, bz, xz_p, M, Isz, Hsz);
    gemm_bias<<<dim3(M / 64, Hsz / 64), blk>>>(x, Wh, bh, xh_p, M, Isz, Hsz);

    dummy_k<<<1, 1>>>();

    mgru_scan<<<Bsz * 4, 256>>>(xz_p, xh_p, Uz, Uh, hs_p);

    gemm_bias<<<dim3(M / 64, Osz / 64), blk>>>(hs_p, Wo, bo, y, M, Hsz, Osz);
}